// round 2
// baseline (speedup 1.0000x reference)
#include <cuda_runtime.h>
#include <cuda_bf16.h>

// Problem constants (match reference)
#define N_CLASSES   4
#define TIME_STEPS  120
#define BATCH       65536
#define DT_MS       10.0f
#define THRESH      0.5f
#define EPS_F       1e-9f

__device__ __forceinline__ float fast_softplus(float x) {
    // stable: max(x,0) + log1p(exp(-|x|)), fast-math MUFU version
    float a = fabsf(x);
    float e = __expf(-a);
    return fmaxf(x, 0.0f) + __logf(1.0f + e);
}

__global__ __launch_bounds__(256)
void acc_race_kernel(const float4* __restrict__ logits4,      // [B] of float4 (C=4)
                     const float*  __restrict__ p_iscale,     // scalar
                     const float*  __restrict__ p_leak,       // [4]
                     const float*  __restrict__ p_se,         // [4]
                     const float*  __restrict__ p_inh,        // scalar
                     const float*  __restrict__ p_ns,         // scalar
                     const float*  __restrict__ p_w,          // [1,1]
                     const float*  __restrict__ p_b,          // [1]
                     const float4* __restrict__ noise4,       // [T*B] of float4
                     float4*       __restrict__ out4)         // [B] of float4
{
    const int b = blockIdx.x * blockDim.x + threadIdx.x;
    if (b >= BATCH) return;

    // ---- load & transform parameters (broadcast loads, L1-hit after first warp) ----
    const float iscale = *p_iscale;
    const float w      = *p_w;
    const float bias   = *p_b;
    const float inh    = fast_softplus(*p_inh);
    const float ns     = fast_softplus(*p_ns);

    float ev[N_CLASSES];    // momentary evidence
    float coef[N_CLASSES];  // se + inh - lk  (fold self-exc, self-inhibition-cancel, leak)
    {
        const float4 lg = logits4[b];
        const float l0 = lg.x, l1 = lg.y, l2 = lg.z, l3 = lg.w;
        ev[0] = fmaf(fmaxf(l0 * iscale, 0.0f), w, bias);
        ev[1] = fmaf(fmaxf(l1 * iscale, 0.0f), w, bias);
        ev[2] = fmaf(fmaxf(l2 * iscale, 0.0f), w, bias);
        ev[3] = fmaf(fmaxf(l3 * iscale, 0.0f), w, bias);
#pragma unroll
        for (int c = 0; c < N_CLASSES; ++c)
            coef[c] = fast_softplus(p_se[c]) + inh - fast_softplus(p_leak[c]);
    }

    // ---- rollout state ----
    float acc[N_CLASSES]   = {0.f, 0.f, 0.f, 0.f};
    float prevS[N_CLASSES] = {0.f, 0.f, 0.f, 0.f};  // s at previous step
    float crossT[N_CLASSES]    = {-1.f, -1.f, -1.f, -1.f};
    float crossPrev[N_CLASSES] = {0.f, 0.f, 0.f, 0.f};
    float crossCur[N_CLASSES]  = {0.f, 0.f, 0.f, 0.f};

    // distance-1 prefetch of noise (coalesced float4 per thread)
    const float4* np = noise4 + b;
    float4 nz = *np;

#pragma unroll 2
    for (int t = 0; t < TIME_STEPS; ++t) {
        float4 nz_next;
        if (t < TIME_STEPS - 1) {
            np += BATCH;
            nz_next = *np;
        } else {
            nz_next = nz;  // dummy, not consumed
        }

        const float total = (acc[0] + acc[1]) + (acc[2] + acc[3]);
        const float nzv[N_CLASSES] = {nz.x, nz.y, nz.z, nz.w};

#pragma unroll
        for (int c = 0; c < N_CLASSES; ++c) {
            // drive = ev + (se+inh-lk)*acc - inh*total + ns*noise
            float drive = fmaf(coef[c], acc[c], ev[c]);
            drive = fmaf(-inh, total, drive);
            drive = fmaf(ns, nzv[c], drive);
            const float sp = fast_softplus(drive);
            // acc' = max(acc + 0.2*(sp - acc), 0) = max(0.8*acc + 0.2*sp, 0)
            const float an = fmaxf(fmaf(0.2f, sp, 0.8f * acc[c]), 0.0f);
            acc[c] = an;

            const float cur = an - THRESH;
            const bool hit = (cur >= 0.0f) && (crossT[c] < 0.0f);
            if (hit) {
                crossT[c]    = (float)t;
                crossPrev[c] = prevS[c];
                crossCur[c]  = cur;
            }
            prevS[c] = cur;
        }
        nz = nz_next;
    }

    // ---- epilogue: interpolate crossing time once per class ----
    float times[N_CLASSES];
#pragma unroll
    for (int c = 0; c < N_CLASSES; ++c) {
        float tm;
        const float tc = crossT[c];
        if (tc >= 0.0f) {
            if (tc > 0.0f) {
                const float prev = crossPrev[c];
                const float cur  = crossCur[c];
                const float frac = -prev / (cur - prev + EPS_F);
                tm = (tc - 1.0f + frac) * DT_MS;
            } else {
                tm = 0.0f;  // idx==0: idx0=0, frac=0
            }
        } else {
            tm = (float)TIME_STEPS * DT_MS;  // never crossed: 1200 ms
        }
        times[c] = tm * 0.001f;  // -> seconds
    }

    out4[b] = make_float4(times[0], times[1], times[2], times[3]);
}

extern "C" void kernel_launch(void* const* d_in, const int* in_sizes, int n_in,
                              void* d_out, int out_size)
{
    const float4* logits = (const float4*)d_in[0];
    const float*  iscale = (const float*)d_in[1];
    const float*  leak   = (const float*)d_in[2];
    const float*  se     = (const float*)d_in[3];
    const float*  inh    = (const float*)d_in[4];
    const float*  ns     = (const float*)d_in[5];
    const float*  pw     = (const float*)d_in[6];
    const float*  pb     = (const float*)d_in[7];
    const float4* noise  = (const float4*)d_in[8];
    float4*       out    = (float4*)d_out;

    const int threads = 256;
    const int blocks  = (BATCH + threads - 1) / threads;  // 256
    acc_race_kernel<<<blocks, threads>>>(logits, iscale, leak, se, inh, ns,
                                         pw, pb, noise, out);
}

// round 4
// speedup vs baseline: 1.4673x; 1.4673x over previous
#include <cuda_runtime.h>
#include <cuda_bf16.h>

// Problem constants (match reference)
#define N_CLASSES   4
#define TIME_STEPS  120
#define BATCH       65536
#define NTHREADS_TOTAL (BATCH * N_CLASSES)   // 262144
#define DT_MS       10.0f
#define THRESH      0.5f
#define EPS_F       1e-9f

__device__ __forceinline__ float fast_softplus(float x) {
    // stable: max(x,0) + log1p(exp(-|x|)), fast-math MUFU version
    float e = __expf(-fabsf(x));
    return fmaxf(x, 0.0f) + __logf(1.0f + e);
}

// One thread per (batch, class). Threads 4b..4b+3 (same lane quad) hold the 4
// classes of batch element b; the cross-class sum is a 2-step shfl butterfly.
__global__ __launch_bounds__(256)
void acc_race_kernel(const float* __restrict__ logits,      // [B*4]
                     const float* __restrict__ p_iscale,    // scalar
                     const float* __restrict__ p_leak,      // [4]
                     const float* __restrict__ p_se,        // [4]
                     const float* __restrict__ p_inh,       // scalar
                     const float* __restrict__ p_ns,        // scalar
                     const float* __restrict__ p_w,         // [1,1]
                     const float* __restrict__ p_b,         // [1]
                     const float* __restrict__ noise,       // [T*B*4]
                     float*       __restrict__ out)         // [B*4]
{
    const int tid = blockIdx.x * blockDim.x + threadIdx.x;   // grid exactly covers
    const int c   = tid & (N_CLASSES - 1);

    // ---- parameters (broadcast / small-vector loads, L1-resident) ----
    const float iscale = *p_iscale;
    const float w      = *p_w;
    const float bias   = *p_b;
    const float inh    = fast_softplus(*p_inh);
    const float ns     = fast_softplus(*p_ns);
    // coef = se + inh - leak  (self-excitation, self-inhibition cancel, leak)
    const float coef   = fast_softplus(p_se[c]) + inh - fast_softplus(p_leak[c]);
    const float ev     = fmaf(fmaxf(logits[tid] * iscale, 0.0f), w, bias);

    // ---- rollout state (scalar per thread) ----
    float acc   = 0.0f;
    float prevS = 0.0f;
    float crossT    = -1.0f;
    float crossPrev = 0.0f;
    float crossCur  = 0.0f;

    // distance-1 prefetch of noise (coalesced: warp reads 32 contiguous floats)
    const float* np = noise + tid;
    float nz = *np;

#pragma unroll 4
    for (int t = 0; t < TIME_STEPS; ++t) {
        float nz_next = nz;
        if (t < TIME_STEPS - 1) {
            np += NTHREADS_TOTAL;
            nz_next = *np;
        }

        // total = sum of acc over the 4 classes of this batch element
        float s     = acc + __shfl_xor_sync(0xffffffffu, acc, 1);
        float total = s   + __shfl_xor_sync(0xffffffffu, s,   2);

        // drive = ev + (se+inh-lk)*acc - inh*total + ns*noise
        float drive = fmaf(coef, acc, ev);
        drive = fmaf(-inh, total, drive);
        drive = fmaf(ns, nz, drive);
        const float sp = fast_softplus(drive);
        // acc' = max(0.8*acc + 0.2*sp, 0)
        acc = fmaxf(fmaf(0.2f, sp, 0.8f * acc), 0.0f);

        const float cur = acc - THRESH;
        const bool hit = (cur >= 0.0f) && (crossT < 0.0f);
        if (hit) {
            crossT    = (float)t;
            crossPrev = prevS;
            crossCur  = cur;
        }
        prevS = cur;
        nz = nz_next;
    }

    // ---- epilogue: interpolate first-crossing time (once) ----
    float tm;
    if (crossT >= 0.0f) {
        if (crossT > 0.0f) {
            const float frac = -crossPrev / (crossCur - crossPrev + EPS_F);
            tm = (crossT - 1.0f + frac) * DT_MS;
        } else {
            tm = 0.0f;  // crossed at idx 0: idx0=0, frac=0
        }
    } else {
        tm = (float)TIME_STEPS * DT_MS;  // never crossed: 1200 ms
    }
    out[tid] = tm * 0.001f;  // -> seconds
}

extern "C" void kernel_launch(void* const* d_in, const int* in_sizes, int n_in,
                              void* d_out, int out_size)
{
    const float* logits = (const float*)d_in[0];
    const float* iscale = (const float*)d_in[1];
    const float* leak   = (const float*)d_in[2];
    const float* se     = (const float*)d_in[3];
    const float* inh    = (const float*)d_in[4];
    const float* ns     = (const float*)d_in[5];
    const float* pw     = (const float*)d_in[6];
    const float* pb     = (const float*)d_in[7];
    const float* noise  = (const float*)d_in[8];
    float*       out    = (float*)d_out;

    const int threads = 256;
    const int blocks  = NTHREADS_TOTAL / threads;  // 1024
    acc_race_kernel<<<blocks, threads>>>(logits, iscale, leak, se, inh, ns,
                                         pw, pb, noise, out);
}

// round 5
// speedup vs baseline: 1.5065x; 1.0267x over previous
#include <cuda_runtime.h>
#include <cuda_bf16.h>

// Problem constants (match reference)
#define N_CLASSES   4
#define TIME_STEPS  120
#define BATCH       65536
#define NTHREADS    (BATCH * 2)          // 131072: one thread per (batch, class-pair)
#define ROW_F2      (BATCH * 2)          // float2 elements per timestep row
#define DT_MS       10.0f
#define THRESH      0.5f
#define EPS_F       1e-9f
#define L2E_F       1.4426950408889634f  // log2(e)
#define LN2_F       0.6931471805599453f

__device__ __forceinline__ float fast_softplus(float x) {
    // parameter transform only (not in hot loop)
    float e = __expf(-fabsf(x));
    return fmaxf(x, 0.0f) + __logf(1.0f + e);
}

// One thread per (batch, class-pair). Thread tid handles flattened elements
// {2*tid, 2*tid+1}; its shuffle partner (lane^1) holds the other class pair of
// the same batch element, so the 4-class sum is local-add + one shfl_xor.
__global__ __launch_bounds__(256)
void acc_race_kernel(const float2* __restrict__ logits2,    // [B*2] float2
                     const float*  __restrict__ p_iscale,
                     const float*  __restrict__ p_leak,     // [4]
                     const float*  __restrict__ p_se,       // [4]
                     const float*  __restrict__ p_inh,
                     const float*  __restrict__ p_ns,
                     const float*  __restrict__ p_w,        // [1,1]
                     const float*  __restrict__ p_b,        // [1]
                     const float2* __restrict__ noise2,     // [T*B*2] float2
                     float2*       __restrict__ out2)       // [B*2] float2
{
    const int tid = blockIdx.x * blockDim.x + threadIdx.x;
    const int c0  = (tid & 1) * 2;      // classes {c0, c0+1}

    // ---- parameters (broadcast loads; transform once) ----
    const float iscale = *p_iscale;
    const float w      = *p_w;
    const float bias   = *p_b;
    const float inh    = fast_softplus(*p_inh);
    const float ns     = fast_softplus(*p_ns);
    // coef = se + inh - leak ; everything feeding the drive is prescaled by
    // log2(e) so the softplus runs natively in base-2 (no EX2/LG2 range muls).
    const float coefp0 = (fast_softplus(p_se[c0])   + inh - fast_softplus(p_leak[c0]))   * L2E_F;
    const float coefp1 = (fast_softplus(p_se[c0+1]) + inh - fast_softplus(p_leak[c0+1])) * L2E_F;
    const float inhp   = inh * L2E_F;
    const float nsp    = ns  * L2E_F;

    const float2 lg = logits2[tid];
    const float evp0 = fmaf(fmaxf(lg.x * iscale, 0.0f), w, bias) * L2E_F;
    const float evp1 = fmaf(fmaxf(lg.y * iscale, 0.0f), w, bias) * L2E_F;

    const float K = 0.2f * LN2_F;       // step constant absorbs the base-2 scale

    // ---- rollout state ----
    float a0 = 0.0f, a1 = 0.0f;
    float cp0 = 0.0f, cc0 = 0.0f, tc0 = 0.0f;   // crossPrev/crossCur (raw acc), step count
    float cp1 = 0.0f, cc1 = 0.0f, tc1 = 0.0f;
    bool  cr0 = false, cr1 = false;

    const float2* np = noise2 + tid;
    float2 nz = *np;

#define STEP_BODY                                                              \
    do {                                                                       \
        const float s     = a0 + a1;                                           \
        const float total = s + __shfl_xor_sync(0xffffffffu, s, 1);            \
        /* class 0 */                                                          \
        float dp0 = fmaf(coefp0, a0, evp0);                                    \
        dp0 = fmaf(-inhp, total, dp0);                                         \
        dp0 = fmaf(nsp, nz.x, dp0);                                            \
        const float e0  = exp2f(-fabsf(dp0));                                  \
        const float sb0 = fmaxf(dp0, 0.0f) + __log2f(1.0f + e0);               \
        a0 = fmaxf(fmaf(K, sb0, 0.8f * a0), 0.0f);                             \
        /* class 1 */                                                          \
        float dp1 = fmaf(coefp1, a1, evp1);                                    \
        dp1 = fmaf(-inhp, total, dp1);                                         \
        dp1 = fmaf(nsp, nz.y, dp1);                                            \
        const float e1  = exp2f(-fabsf(dp1));                                  \
        const float sb1 = fmaxf(dp1, 0.0f) + __log2f(1.0f + e1);               \
        a1 = fmaxf(fmaf(K, sb1, 0.8f * a1), 0.0f);                             \
        /* crossing bookkeeping: overwrite until crossed, then freeze */       \
        const bool nc0 = !cr0;                                                 \
        cp0 = nc0 ? cc0 : cp0;                                                 \
        cc0 = nc0 ? a0  : cc0;                                                 \
        tc0 = nc0 ? tc0 + 1.0f : tc0;                                          \
        cr0 = cr0 || (a0 >= THRESH);                                           \
        const bool nc1 = !cr1;                                                 \
        cp1 = nc1 ? cc1 : cp1;                                                 \
        cc1 = nc1 ? a1  : cc1;                                                 \
        tc1 = nc1 ? tc1 + 1.0f : tc1;                                          \
        cr1 = cr1 || (a1 >= THRESH);                                           \
    } while (0)

    // 119 prefetching iterations (119 = 7*17, unrolls evenly) + 1 peeled tail
#pragma unroll 7
    for (int t = 0; t < TIME_STEPS - 1; ++t) {
        np += ROW_F2;
        const float2 nz_next = *np;
        STEP_BODY;
        nz = nz_next;
    }
    STEP_BODY;   // t = 119, no prefetch
#undef STEP_BODY

    // ---- epilogue: interpolate first-crossing time ----
    // frac = (THRESH - accPrev) / (accCur - accPrev + EPS): THRESH cancels in
    // the denominator, so raw acc values were stored.
    float t0, t1;
    if (cr0) {
        const float idx = tc0 - 1.0f;   // first crossing index
        t0 = (idx > 0.0f)
               ? (idx - 1.0f + (THRESH - cp0) / (cc0 - cp0 + EPS_F)) * DT_MS
               : 0.0f;
    } else {
        t0 = (float)TIME_STEPS * DT_MS;
    }
    if (cr1) {
        const float idx = tc1 - 1.0f;
        t1 = (idx > 0.0f)
               ? (idx - 1.0f + (THRESH - cp1) / (cc1 - cp1 + EPS_F)) * DT_MS
               : 0.0f;
    } else {
        t1 = (float)TIME_STEPS * DT_MS;
    }

    out2[tid] = make_float2(t0 * 0.001f, t1 * 0.001f);
}

extern "C" void kernel_launch(void* const* d_in, const int* in_sizes, int n_in,
                              void* d_out, int out_size)
{
    const float2* logits = (const float2*)d_in[0];
    const float*  iscale = (const float*)d_in[1];
    const float*  leak   = (const float*)d_in[2];
    const float*  se     = (const float*)d_in[3];
    const float*  inh    = (const float*)d_in[4];
    const float*  ns     = (const float*)d_in[5];
    const float*  pw     = (const float*)d_in[6];
    const float*  pb     = (const float*)d_in[7];
    const float2* noise  = (const float2*)d_in[8];
    float2*       out    = (float2*)d_out;

    const int threads = 256;
    const int blocks  = NTHREADS / threads;   // 512
    acc_race_kernel<<<blocks, threads>>>(logits, iscale, leak, se, inh, ns,
                                         pw, pb, noise, out);
}

// round 6
// speedup vs baseline: 1.6217x; 1.0765x over previous
#include <cuda_runtime.h>
#include <cuda_bf16.h>

// Problem constants (match reference)
#define N_CLASSES   4
#define TIME_STEPS  120
#define BATCH       65536
#define NTHREADS    (BATCH * N_CLASSES)   // 262144: one thread per (batch, class)
#define DT_MS       10.0f
#define THRESH      0.5f
#define EPS_F       1e-9f
#define L2E_F       1.4426950408889634f   // log2(e)
#define LN2_F       0.6931471805599453f

__device__ __forceinline__ float fast_softplus(float x) {
    // parameter transform only (not in hot loop)
    float e = __expf(-fabsf(x));
    return fmaxf(x, 0.0f) + __logf(1.0f + e);
}

// One thread per (batch, class). Threads 4b..4b+3 (one lane quad) hold the 4
// classes of batch element b; cross-class sum = 2-step shfl butterfly.
// All drive coefficients are prescaled by log2(e) so softplus runs natively
// in base 2 (EX2/LG2 with no range-conversion multiplies); the 0.2 Euler step
// absorbs the ln2 rescale.
__global__ __launch_bounds__(256)
void acc_race_kernel(const float* __restrict__ logits,      // [B*4]
                     const float* __restrict__ p_iscale,
                     const float* __restrict__ p_leak,      // [4]
                     const float* __restrict__ p_se,        // [4]
                     const float* __restrict__ p_inh,
                     const float* __restrict__ p_ns,
                     const float* __restrict__ p_w,         // [1,1]
                     const float* __restrict__ p_b,         // [1]
                     const float* __restrict__ noise,       // [T*B*4]
                     float*       __restrict__ out)         // [B*4]
{
    const int tid = blockIdx.x * blockDim.x + threadIdx.x;
    const int c   = tid & (N_CLASSES - 1);

    // ---- parameters (broadcast loads; transform once) ----
    const float iscale = *p_iscale;
    const float w      = *p_w;
    const float bias   = *p_b;
    const float inh    = fast_softplus(*p_inh);
    const float ns     = fast_softplus(*p_ns);
    // coef = se + inh - leak, prescaled to base-2 domain
    const float coefp = (fast_softplus(p_se[c]) + inh - fast_softplus(p_leak[c])) * L2E_F;
    const float inhp  = inh * L2E_F;
    const float nsp   = ns  * L2E_F;
    const float evp   = fmaf(fmaxf(logits[tid] * iscale, 0.0f), w, bias) * L2E_F;
    const float K     = 0.2f * LN2_F;   // step constant absorbs base-2 scale

    // ---- rollout state ----
    float acc = 0.0f;
    float cp = 0.0f, cc = 0.0f, tc = 0.0f;  // crossPrev/crossCur (raw acc), step count
    bool  cr = false;

    const float* np = noise + tid;
    float nz = *np;

#define STEP_BODY                                                             \
    do {                                                                      \
        float s     = acc + __shfl_xor_sync(0xffffffffu, acc, 1);             \
        float total = s   + __shfl_xor_sync(0xffffffffu, s,   2);             \
        float dp = fmaf(coefp, acc, evp);                                     \
        dp = fmaf(-inhp, total, dp);                                          \
        dp = fmaf(nsp, nz, dp);                                               \
        const float e  = exp2f(-fabsf(dp));                                   \
        const float sb = fmaxf(dp, 0.0f) + __log2f(1.0f + e);                 \
        acc = fmaxf(fmaf(K, sb, 0.8f * acc), 0.0f);                           \
        /* crossing bookkeeping: overwrite until crossed, then freeze */      \
        const bool nc = !cr;                                                  \
        cp = nc ? cc : cp;                                                    \
        cc = nc ? acc : cc;                                                   \
        tc = nc ? tc + 1.0f : tc;                                             \
        cr = cr || (acc >= THRESH);                                           \
    } while (0)

    // 119 prefetching iterations (119 = 7*17, unrolls evenly) + 1 peeled tail
#pragma unroll 7
    for (int t = 0; t < TIME_STEPS - 1; ++t) {
        np += NTHREADS;
        const float nz_next = *np;
        STEP_BODY;
        nz = nz_next;
    }
    STEP_BODY;   // t = 119, no prefetch
#undef STEP_BODY

    // ---- epilogue: interpolate first-crossing time ----
    // prev = cp - THRESH, cur = cc - THRESH; THRESH cancels in denominator.
    float tm;
    if (cr) {
        const float idx = tc - 1.0f;    // first crossing index (float)
        tm = (idx > 0.0f)
               ? (idx - 1.0f + (THRESH - cp) / (cc - cp + EPS_F)) * DT_MS
               : 0.0f;                  // crossed at idx 0
    } else {
        tm = (float)TIME_STEPS * DT_MS; // never crossed: 1200 ms
    }
    out[tid] = tm * 0.001f;             // -> seconds
}

extern "C" void kernel_launch(void* const* d_in, const int* in_sizes, int n_in,
                              void* d_out, int out_size)
{
    const float* logits = (const float*)d_in[0];
    const float* iscale = (const float*)d_in[1];
    const float* leak   = (const float*)d_in[2];
    const float* se     = (const float*)d_in[3];
    const float* inh    = (const float*)d_in[4];
    const float* ns     = (const float*)d_in[5];
    const float* pw     = (const float*)d_in[6];
    const float* pb     = (const float*)d_in[7];
    const float* noise  = (const float*)d_in[8];
    float*       out    = (float*)d_out;

    const int threads = 256;
    const int blocks  = NTHREADS / threads;   // 1024
    acc_race_kernel<<<blocks, threads>>>(logits, iscale, leak, se, inh, ns,
                                         pw, pb, noise, out);
}